// round 1
// baseline (speedup 1.0000x reference)
#include <cuda_runtime.h>
#include <math.h>

#define NN 16384      // B*L nodes
#define BATCH 32
#define SEQ 512
#define HIDDIM 768
#define CH 32         // H1*C1
#define VSZ 8192
#define LAB 10

// ---------------- device scratch (no allocation allowed) ----------------
__device__ float g_h1[NN*CH];
__device__ float g_as1[NN*2];
__device__ float g_ad1[NN*2];
__device__ float g_r[2][NN*CH];
__device__ float g_as2[2][NN];
__device__ float g_ad2[2][NN];
__device__ float g_w2s[CH];
__device__ float g_w2d[CH];
__device__ float g_zpart[2][BATCH][4][CH];
__device__ float g_pooled[64*HIDDIM];   // [br*32+b][768]
__device__ float g_outv[64*HIDDIM];     // tanh output
__device__ float g_logits[64*LAB];
__device__ float g_invnorm[64];
__device__ float g_rowloss[64];

__device__ __forceinline__ float lrelu(float x){ return x > 0.f ? x : 0.2f*x; }

// ---------------- K0: w2s = W2 @ att_src2, w2d = W2 @ att_dst2 ----------------
__global__ void k0_prep(const float* __restrict__ W2,
                        const float* __restrict__ att_src2,
                        const float* __restrict__ att_dst2) {
    int lane = threadIdx.x & 31, w = threadIdx.x >> 5;
    for (int c = w; c < CH; c += 8) {
        float ss = 0.f, sd = 0.f;
        for (int k = lane; k < HIDDIM; k += 32) {
            float wv = W2[c*HIDDIM + k];
            ss += wv * att_src2[k];
            sd += wv * att_dst2[k];
        }
        #pragma unroll
        for (int o = 16; o; o >>= 1) {
            ss += __shfl_xor_sync(0xffffffffu, ss, o);
            sd += __shfl_xor_sync(0xffffffffu, sd, o);
        }
        if (!lane) { g_w2s[c] = ss; g_w2d[c] = sd; }
    }
}

// ---------------- K1: h1 = features @ W1  (16384x768 * 768x32) ----------------
// block tile 128x32, 256 threads, thread tile 4x4, k-chunk 32
__global__ void k1_gemm1(const float* __restrict__ feat, const float* __restrict__ W1) {
    __shared__ float As[128][33];
    __shared__ float Bs[32][32];
    int tid = threadIdx.x;
    int tx = tid & 7, ty = tid >> 3;           // tx: col group (8), ty: row group (32)
    int rowBase = blockIdx.x * 128;
    float acc[4][4] = {};
    for (int kb = 0; kb < HIDDIM; kb += 32) {
        #pragma unroll
        for (int q = 0; q < 4; q++) {
            int lin = tid + 256*q;             // 0..1023
            int r = lin >> 3, s = lin & 7;
            float4 v = *(const float4*)&feat[(size_t)(rowBase + r)*HIDDIM + kb + s*4];
            As[r][s*4+0]=v.x; As[r][s*4+1]=v.y; As[r][s*4+2]=v.z; As[r][s*4+3]=v.w;
        }
        {
            int kk = tid >> 3, s = tid & 7;
            float4 v = *(const float4*)&W1[(kb+kk)*CH + s*4];
            *(float4*)&Bs[kk][s*4] = v;
        }
        __syncthreads();
        #pragma unroll
        for (int kk = 0; kk < 32; kk++) {
            float a[4];
            #pragma unroll
            for (int i = 0; i < 4; i++) a[i] = As[ty*4+i][kk];
            float4 bv = *(float4*)&Bs[kk][tx*4];
            float b[4] = {bv.x, bv.y, bv.z, bv.w};
            #pragma unroll
            for (int i = 0; i < 4; i++)
                #pragma unroll
                for (int j = 0; j < 4; j++) acc[i][j] += a[i]*b[j];
        }
        __syncthreads();
    }
    #pragma unroll
    for (int i = 0; i < 4; i++) {
        int r = rowBase + ty*4 + i;
        float4 v = {acc[i][0], acc[i][1], acc[i][2], acc[i][3]};
        *(float4*)&g_h1[r*CH + tx*4] = v;
    }
}

// ---------------- K1b: a_s1, a_d1 per node/head ----------------
__global__ void k1b_att(const float* __restrict__ att_src1, const float* __restrict__ att_dst1) {
    int wid = (blockIdx.x*blockDim.x + threadIdx.x) >> 5;
    int lane = threadIdx.x & 31;
    if (wid >= NN) return;
    float h = g_h1[wid*CH + lane];
    float vs = h * att_src1[lane];
    float vd = h * att_dst1[lane];
    #pragma unroll
    for (int o = 8; o; o >>= 1) {
        vs += __shfl_xor_sync(0xffffffffu, vs, o);
        vd += __shfl_xor_sync(0xffffffffu, vd, o);
    }
    if ((lane & 15) == 0) {
        g_as1[wid*2 + (lane>>4)] = vs;
        g_ad1[wid*2 + (lane>>4)] = vd;
    }
}

// ---------------- K2: conv1 aggregate (both branches) + relu + conv2 attn dots -------
__global__ void k2_conv1(const int* __restrict__ tokA, const int* __restrict__ tokB,
                         const float* __restrict__ EM, const float* __restrict__ b1) {
    int i = (blockIdx.x*blockDim.x + threadIdx.x) >> 5;
    int lane = threadIdx.x & 31;
    if (i >= NN) return;
    int pos = i & (SEQ-1);
    bool hasP = pos > 0, hasN = pos < SEQ-1;
    int hh = lane >> 4;   // head for this channel

    float adi = g_ad1[i*2 + hh];
    float es = lrelu(g_as1[i*2 + hh] + adi);
    float ep = hasP ? lrelu(g_as1[(i-1)*2 + hh] + adi) : -1e30f;
    float en = hasN ? lrelu(g_as1[(i+1)*2 + hh] + adi) : -1e30f;
    float m  = fmaxf(es, fmaxf(ep, en));
    float xs = expf(es - m);
    float xp = hasP ? expf(ep - m) : 0.f;
    float xn = hasN ? expf(en - m) : 0.f;
    float inv = 1.f / (xs + xp + xn + 1e-16f);
    float as_ = xs*inv, ap = xp*inv, an = xn*inv;

    int ti1 = tokA[i], ti2 = tokB[i];
    float ewp1=0.f, ewn1=0.f, ewp2=0.f, ewn2=0.f;
    if (hasP) { ewp1 = EM[tokA[i-1]*VSZ + ti1]; ewp2 = EM[tokB[i-1]*VSZ + ti2]; }
    if (hasN) { ewn1 = EM[tokA[i+1]*VSZ + ti1]; ewn2 = EM[tokB[i+1]*VSZ + ti2]; }

    float hp = hasP ? g_h1[(i-1)*CH + lane] : 0.f;
    float hs = g_h1[i*CH + lane];
    float hn = hasN ? g_h1[(i+1)*CH + lane] : 0.f;
    float bb = b1[lane];

    float r1 = fmaxf(0.f, ap*ewp1*hp + as_*hs + an*ewn1*hn + bb);
    float r2 = fmaxf(0.f, ap*ewp2*hp + as_*hs + an*ewn2*hn + bb);
    g_r[0][i*CH + lane] = r1;
    g_r[1][i*CH + lane] = r2;

    float ws2 = g_w2s[lane], wd2 = g_w2d[lane];
    float v0 = r1*ws2, v1 = r1*wd2, v2 = r2*ws2, v3 = r2*wd2;
    #pragma unroll
    for (int o = 16; o; o >>= 1) {
        v0 += __shfl_xor_sync(0xffffffffu, v0, o);
        v1 += __shfl_xor_sync(0xffffffffu, v1, o);
        v2 += __shfl_xor_sync(0xffffffffu, v2, o);
        v3 += __shfl_xor_sync(0xffffffffu, v3, o);
    }
    if (!lane) {
        g_as2[0][i] = v0; g_ad2[0][i] = v1;
        g_as2[1][i] = v2; g_ad2[1][i] = v3;
    }
}

// ---------------- K3: conv2 aggregate + pooled partial sums ----------------
__global__ void k3_zpart() {
    int b = blockIdx.x, q = blockIdx.y;
    int w = threadIdx.x >> 5, lane = threadIdx.x & 31;
    float acc0 = 0.f, acc1 = 0.f;
    for (int pp = w; pp < 128; pp += 8) {
        int pos = q*128 + pp;
        int i = b*SEQ + pos;
        bool hasP = pos > 0, hasN = pos < SEQ-1;
        #pragma unroll
        for (int br = 0; br < 2; br++) {
            float adi = g_ad2[br][i];
            float es = lrelu(g_as2[br][i] + adi);
            float ep = hasP ? lrelu(g_as2[br][i-1] + adi) : -1e30f;
            float en = hasN ? lrelu(g_as2[br][i+1] + adi) : -1e30f;
            float m  = fmaxf(es, fmaxf(ep, en));
            float xs = expf(es - m);
            float xp = hasP ? expf(ep - m) : 0.f;
            float xn = hasN ? expf(en - m) : 0.f;
            float inv = 1.f / (xs + xp + xn + 1e-16f);
            float z = xs*inv * g_r[br][i*CH + lane];
            if (hasP) z += xp*inv * g_r[br][(i-1)*CH + lane];
            if (hasN) z += xn*inv * g_r[br][(i+1)*CH + lane];
            if (br == 0) acc0 += z; else acc1 += z;
        }
    }
    __shared__ float sm[2][8][CH];
    sm[0][w][lane] = acc0;
    sm[1][w][lane] = acc1;
    __syncthreads();
    if (w < 2) {
        float s = 0.f;
        #pragma unroll
        for (int t = 0; t < 8; t++) s += sm[w][t][lane];
        g_zpart[w][b][q][lane] = s;
    }
}

// ---------------- K4a: pooled = zbar @ W2 + b2 ----------------
__global__ void k4a_pooled(const float* __restrict__ W2, const float* __restrict__ b2) {
    int blk = blockIdx.x; int br = blk >> 5, b = blk & 31;
    __shared__ float z[CH];
    if (threadIdx.x < CH) {
        float s = g_zpart[br][b][0][threadIdx.x] + g_zpart[br][b][1][threadIdx.x]
                + g_zpart[br][b][2][threadIdx.x] + g_zpart[br][b][3][threadIdx.x];
        z[threadIdx.x] = s * (1.f/512.f);
    }
    __syncthreads();
    for (int j = threadIdx.x; j < HIDDIM; j += 256) {
        float acc = b2[j];
        #pragma unroll
        for (int c = 0; c < CH; c++) acc += z[c] * W2[c*HIDDIM + j];
        g_pooled[(br*32 + b)*HIDDIM + j] = acc;
    }
}

// ---------------- K4b: out = tanh(pooled @ Wo1 + bo1), M=64 K=768 N=768 ----------------
__global__ void k4b_out(const float* __restrict__ Wo1, const float* __restrict__ bo1) {
    __shared__ float As[16][64];
    __shared__ float Bs[64][16];
    int tx = threadIdx.x, ty = threadIdx.y;
    int tid = ty*16 + tx;
    int row = blockIdx.y*16 + ty;
    int col = blockIdx.x*16 + tx;
    float acc = 0.f;
    for (int kb = 0; kb < HIDDIM; kb += 64) {
        #pragma unroll
        for (int q = 0; q < 4; q++) {
            int lin = tid + 256*q; int r = lin >> 6, k = lin & 63;
            As[r][k] = g_pooled[(blockIdx.y*16 + r)*HIDDIM + kb + k];
        }
        #pragma unroll
        for (int q = 0; q < 4; q++) {
            int lin = tid + 256*q; int k = lin >> 4, c = lin & 15;
            Bs[k][c] = Wo1[(kb + k)*HIDDIM + blockIdx.x*16 + c];
        }
        __syncthreads();
        #pragma unroll
        for (int kk = 0; kk < 64; kk++) acc += As[ty][kk] * Bs[kk][tx];
        __syncthreads();
    }
    g_outv[row*HIDDIM + col] = tanhf(acc + bo1[col]);
}

// ---------------- K4c: logits = out @ Wo2 + bo2 ----------------
__global__ void k4c_logits(const float* __restrict__ Wo2, const float* __restrict__ bo2) {
    int gw = (blockIdx.x*256 + threadIdx.x) >> 5;
    int lane = threadIdx.x & 31;
    if (gw >= 64*LAB) return;
    int lab = gw % LAB, rb = gw / LAB;
    float s = 0.f;
    for (int k = lane; k < HIDDIM; k += 32) s += g_outv[rb*HIDDIM + k] * Wo2[k*LAB + lab];
    #pragma unroll
    for (int o = 16; o; o >>= 1) s += __shfl_xor_sync(0xffffffffu, s, o);
    if (!lane) g_logits[rb*LAB + lab] = s + bo2[lab];
}

// ---------------- K5a: row inverse norms of interleaved p ----------------
__global__ void k5a_norm() {
    int y = (blockIdx.x*256 + threadIdx.x) >> 5;
    int lane = threadIdx.x & 31;
    if (y >= 64) return;
    int br = y & 1, b = y >> 1;
    const float* p = &g_outv[(br*32 + b)*HIDDIM];
    float s = 0.f;
    for (int k = lane; k < HIDDIM; k += 32) s += p[k]*p[k];
    #pragma unroll
    for (int o = 16; o; o >>= 1) s += __shfl_xor_sync(0xffffffffu, s, o);
    if (!lane) g_invnorm[y] = 1.f / fmaxf(sqrtf(s), 1e-8f);
}

// ---------------- K5b: SimCSE row loss ----------------
__global__ void k5b_sim() {
    int y = blockIdx.x;
    __shared__ float py[HIDDIM];
    __shared__ float sims[64];
    int bry = y & 1, by = y >> 1;
    const float* prow = &g_outv[(bry*32 + by)*HIDDIM];
    for (int k = threadIdx.x; k < HIDDIM; k += 256) py[k] = prow[k];
    __syncthreads();
    int w = threadIdx.x >> 5, lane = threadIdx.x & 31;
    float invy = g_invnorm[y];
    for (int c = w; c < 64; c += 8) {
        const float* pc = &g_outv[((c & 1)*32 + (c >> 1))*HIDDIM];
        float s = 0.f;
        for (int k = lane; k < HIDDIM; k += 32) s += py[k]*pc[k];
        #pragma unroll
        for (int o = 16; o; o >>= 1) s += __shfl_xor_sync(0xffffffffu, s, o);
        if (!lane) {
            float v = s * invy * g_invnorm[c];
            if (c == y) v -= 1e12f;
            sims[c] = v * 20.0f;   // / 0.05
        }
    }
    __syncthreads();
    if (threadIdx.x < 32) {
        float a = sims[threadIdx.x], bb = sims[threadIdx.x + 32];
        float m = fmaxf(a, bb);
        #pragma unroll
        for (int o = 16; o; o >>= 1) m = fmaxf(m, __shfl_xor_sync(0xffffffffu, m, o));
        float e = expf(a - m) + expf(bb - m);
        #pragma unroll
        for (int o = 16; o; o >>= 1) e += __shfl_xor_sync(0xffffffffu, e, o);
        if (threadIdx.x == 0) {
            float lse = m + logf(e);
            int partner = (y & 1) ? (y - 1) : (y + 1);
            g_rowloss[y] = -(sims[partner] - lse);
        }
    }
}

// ---------------- K6: NLL + total loss + output write ----------------
__global__ void k6_final(const int* __restrict__ label, float* __restrict__ out, int out_size) {
    __shared__ float nl[64];
    int t = threadIdx.x;
    if (t < 64) {
        const float* lg = &g_logits[t*LAB];
        float m = -1e30f;
        #pragma unroll
        for (int j = 0; j < LAB; j++) m = fmaxf(m, lg[j]);
        float e = 0.f;
        #pragma unroll
        for (int j = 0; j < LAB; j++) e += expf(lg[j] - m);
        float lse = m + logf(e);
        nl[t] = -(lg[label[t % 32]] - lse);
    }
    __syncthreads();
    int base = (out_size > 320) ? 1 : 0;
    if (t == 0 && base == 1) {
        float l1 = 0.f, l2 = 0.f, sl = 0.f;
        for (int j = 0; j < 32; j++) { l1 += nl[j]; l2 += nl[32 + j]; }
        for (int j = 0; j < 64; j++) sl += g_rowloss[j];
        out[0] = l1*(1.f/32.f) + l2*(1.f/32.f) + sl*(1.f/64.f);
    }
    for (int k = t; k < 320 && (base + k) < out_size; k += 256)
        out[base + k] = g_logits[k];   // branch-0 logits
}

extern "C" void kernel_launch(void* const* d_in, const int* in_sizes, int n_in,
                              void* d_out, int out_size) {
    const int*   src    = (const int*)  d_in[0];
    const int*   other  = (const int*)  d_in[1];
    const int*   label  = (const int*)  d_in[2];
    const float* feat   = (const float*)d_in[3];
    const float* EM     = (const float*)d_in[4];
    const float* W1     = (const float*)d_in[5];
    const float* asrc1  = (const float*)d_in[6];
    const float* adst1  = (const float*)d_in[7];
    const float* b1     = (const float*)d_in[8];
    const float* W2     = (const float*)d_in[9];
    const float* asrc2  = (const float*)d_in[10];
    const float* adst2  = (const float*)d_in[11];
    const float* b2     = (const float*)d_in[12];
    const float* Wo1    = (const float*)d_in[13];
    const float* bo1    = (const float*)d_in[14];
    const float* Wo2    = (const float*)d_in[15];
    const float* bo2    = (const float*)d_in[16];
    float* out = (float*)d_out;

    k0_prep<<<1, 256>>>(W2, asrc2, adst2);
    k1_gemm1<<<NN/128, 256>>>(feat, W1);
    k1b_att<<<NN/8, 256>>>(asrc1, adst1);
    k2_conv1<<<NN/8, 256>>>(src, other, EM, b1);
    k3_zpart<<<dim3(BATCH, 4), 256>>>();
    k4a_pooled<<<64, 256>>>(W2, b2);
    k4b_out<<<dim3(48, 4), dim3(16, 16)>>>(Wo1, bo1);
    k4c_logits<<<80, 256>>>(Wo2, bo2);
    k5a_norm<<<8, 256>>>();
    k5b_sim<<<64, 256>>>();
    k6_final<<<1, 256>>>(label, out, out_size);
}

// round 2
// speedup vs baseline: 1.0529x; 1.0529x over previous
#include <cuda_runtime.h>
#include <math.h>

#define NN 16384
#define BATCH 32
#define SEQ 512
#define HIDDIM 768
#define CH 32
#define VSZ 8192
#define LAB 10

// ---------------- device scratch ----------------
__device__ float g_h1[NN*CH];
__device__ float g_as1[NN*2];
__device__ float g_ad1[NN*2];
__device__ float g_w2s[CH];
__device__ float g_w2d[CH];
__device__ float g_pooled[64*HIDDIM];
__device__ float g_outv[64*HIDDIM];
__device__ float g_loss;
__device__ int   g_ticket;

__device__ __forceinline__ float lrelu(float x){ return x > 0.f ? x : 0.2f*x; }

// ================= K1: h1 = feat@W1 + att1 epilogue; block 128 = prep =================
__global__ void k1_fused(const float* __restrict__ feat, const float* __restrict__ W1,
                         const float* __restrict__ W2,
                         const float* __restrict__ att_src2, const float* __restrict__ att_dst2,
                         const float* __restrict__ att_src1, const float* __restrict__ att_dst1) {
    if (blockIdx.x == 128) {
        // prep: w2s/w2d + zero accumulators
        int lane = threadIdx.x & 31, w = threadIdx.x >> 5;
        if (threadIdx.x == 0) { g_loss = 0.f; g_ticket = 0; }
        for (int c = w; c < CH; c += 8) {
            float ss = 0.f, sd = 0.f;
            for (int k = lane; k < HIDDIM; k += 32) {
                float wv = W2[c*HIDDIM + k];
                ss += wv * att_src2[k];
                sd += wv * att_dst2[k];
            }
            #pragma unroll
            for (int o = 16; o; o >>= 1) {
                ss += __shfl_xor_sync(0xffffffffu, ss, o);
                sd += __shfl_xor_sync(0xffffffffu, sd, o);
            }
            if (!lane) { g_w2s[c] = ss; g_w2d[c] = sd; }
        }
        return;
    }
    __shared__ float As[128][33];
    __shared__ float Bs[32][32];
    int tid = threadIdx.x;
    int tx = tid & 7, ty = tid >> 3;
    int rowBase = blockIdx.x * 128;
    float acc[4][4] = {};
    for (int kb = 0; kb < HIDDIM; kb += 32) {
        #pragma unroll
        for (int q = 0; q < 4; q++) {
            int lin = tid + 256*q;
            int r = lin >> 3, s = lin & 7;
            float4 v = *(const float4*)&feat[(size_t)(rowBase + r)*HIDDIM + kb + s*4];
            As[r][s*4+0]=v.x; As[r][s*4+1]=v.y; As[r][s*4+2]=v.z; As[r][s*4+3]=v.w;
        }
        {
            int kk = tid >> 3, s = tid & 7;
            float4 v = *(const float4*)&W1[(kb+kk)*CH + s*4];
            *(float4*)&Bs[kk][s*4] = v;
        }
        __syncthreads();
        #pragma unroll
        for (int kk = 0; kk < 32; kk++) {
            float a[4];
            #pragma unroll
            for (int i = 0; i < 4; i++) a[i] = As[ty*4+i][kk];
            float4 bv = *(float4*)&Bs[kk][tx*4];
            float b[4] = {bv.x, bv.y, bv.z, bv.w};
            #pragma unroll
            for (int i = 0; i < 4; i++)
                #pragma unroll
                for (int j = 0; j < 4; j++) acc[i][j] += a[i]*b[j];
        }
        __syncthreads();
    }
    // att_src1/att_dst1 vectors over this thread's 4 channels
    float vs[4], vd[4];
    #pragma unroll
    for (int j = 0; j < 4; j++) { vs[j] = att_src1[tx*4+j]; vd[j] = att_dst1[tx*4+j]; }
    #pragma unroll
    for (int i = 0; i < 4; i++) {
        int r = rowBase + ty*4 + i;
        float4 v = {acc[i][0], acc[i][1], acc[i][2], acc[i][3]};
        *(float4*)&g_h1[r*CH + tx*4] = v;
        // per-row attention dots: sum over 32 channels held by 8 consecutive lanes;
        // heads split: tx 0..3 = head0, tx 4..7 = head1 -> reduce within groups of 4 lanes
        float ss = acc[i][0]*vs[0] + acc[i][1]*vs[1] + acc[i][2]*vs[2] + acc[i][3]*vs[3];
        float sd = acc[i][0]*vd[0] + acc[i][1]*vd[1] + acc[i][2]*vd[2] + acc[i][3]*vd[3];
        ss += __shfl_xor_sync(0xffffffffu, ss, 1);
        ss += __shfl_xor_sync(0xffffffffu, ss, 2);
        sd += __shfl_xor_sync(0xffffffffu, sd, 1);
        sd += __shfl_xor_sync(0xffffffffu, sd, 2);
        if ((tx & 3) == 0) {
            g_as1[r*2 + (tx>>2)] = ss;
            g_ad1[r*2 + (tx>>2)] = sd;
        }
    }
}

// ================= K2: per-sequence conv1+conv2+pool+pooled-GEMM =================
// grid 32 (one per sequence), block 512, dyn smem 151552 B
__global__ void k2_seq(const int* __restrict__ tokA, const int* __restrict__ tokB,
                       const float* __restrict__ EM, const float* __restrict__ b1,
                       const float* __restrict__ W2, const float* __restrict__ b2) {
    extern __shared__ float sm[];
    float* r0   = sm;                 // [512*32]
    float* r1   = sm + 16384;         // [512*32]
    float* ew   = sm + 32768;         // [4*512]  ewp1, ewn1, ewp2, ewn2
    float* as2_ = sm + 34816;         // [2*512]
    float* ad2_ = sm + 35840;         // [2*512]
    float* zr   = sm + 36864;         // [2*16*32]

    int b = blockIdx.x;
    int base = b * SEQ;
    int t = threadIdx.x;
    int w = t >> 5, lane = t & 31;

    // Phase A0: edge-weight gathers (thread = node)
    {
        int i = base + t;
        int ta = tokA[i], tb = tokB[i];
        bool hasP = t > 0, hasN = t < SEQ-1;
        ew[t]        = hasP ? EM[tokA[i-1]*VSZ + ta] : 0.f;
        ew[512 + t]  = hasN ? EM[tokA[i+1]*VSZ + ta] : 0.f;
        ew[1024 + t] = hasP ? EM[tokB[i-1]*VSZ + tb] : 0.f;
        ew[1536 + t] = hasN ? EM[tokB[i+1]*VSZ + tb] : 0.f;
    }
    float bb = b1[lane];
    float ws2 = g_w2s[lane], wd2 = g_w2d[lane];
    __syncthreads();

    // Phase A1: conv1 aggregate + relu + conv2 attention dots (warp = node)
    int head = lane >> 4;
    for (int n = w; n < SEQ; n += 16) {
        int i = base + n;
        bool hasP = n > 0, hasN = n < SEQ-1;
        float adi = g_ad1[i*2 + head];
        float es = lrelu(g_as1[i*2 + head] + adi);
        float ep = hasP ? lrelu(g_as1[(i-1)*2 + head] + adi) : -1e30f;
        float en = hasN ? lrelu(g_as1[(i+1)*2 + head] + adi) : -1e30f;
        float m  = fmaxf(es, fmaxf(ep, en));
        float xs = expf(es - m);
        float xp = hasP ? expf(ep - m) : 0.f;
        float xn = hasN ? expf(en - m) : 0.f;
        float inv = 1.f / (xs + xp + xn + 1e-16f);
        float as_ = xs*inv, ap = xp*inv, an = xn*inv;

        float hp = hasP ? g_h1[(i-1)*CH + lane] : 0.f;
        float hs = g_h1[i*CH + lane];
        float hn = hasN ? g_h1[(i+1)*CH + lane] : 0.f;

        float rv0 = fmaxf(0.f, ap*ew[n]*hp      + as_*hs + an*ew[512+n]*hn  + bb);
        float rv1 = fmaxf(0.f, ap*ew[1024+n]*hp + as_*hs + an*ew[1536+n]*hn + bb);
        r0[n*CH + lane] = rv0;
        r1[n*CH + lane] = rv1;

        float v0 = rv0*ws2, v1 = rv0*wd2, v2 = rv1*ws2, v3 = rv1*wd2;
        #pragma unroll
        for (int o = 16; o; o >>= 1) {
            v0 += __shfl_xor_sync(0xffffffffu, v0, o);
            v1 += __shfl_xor_sync(0xffffffffu, v1, o);
            v2 += __shfl_xor_sync(0xffffffffu, v2, o);
            v3 += __shfl_xor_sync(0xffffffffu, v3, o);
        }
        if (!lane) {
            as2_[n] = v0;       ad2_[n] = v1;
            as2_[512+n] = v2;   ad2_[512+n] = v3;
        }
    }
    __syncthreads();

    // Phase B: conv2 aggregate, accumulate mean-pool partials per lane
    float accA = 0.f, accB = 0.f;
    for (int n = w; n < SEQ; n += 16) {
        bool hasP = n > 0, hasN = n < SEQ-1;
        #pragma unroll
        for (int br = 0; br < 2; br++) {
            const float* rr = br ? r1 : r0;
            int o = br*512;
            float adi = ad2_[o + n];
            float es = lrelu(as2_[o + n] + adi);
            float ep = hasP ? lrelu(as2_[o + n-1] + adi) : -1e30f;
            float en = hasN ? lrelu(as2_[o + n+1] + adi) : -1e30f;
            float m  = fmaxf(es, fmaxf(ep, en));
            float xs = expf(es - m);
            float xp = hasP ? expf(ep - m) : 0.f;
            float xn = hasN ? expf(en - m) : 0.f;
            float inv = 1.f / (xs + xp + xn + 1e-16f);
            float z = xs*inv * rr[n*CH + lane];
            if (hasP) z += xp*inv * rr[(n-1)*CH + lane];
            if (hasN) z += xn*inv * rr[(n+1)*CH + lane];
            if (br == 0) accA += z; else accB += z;
        }
    }
    zr[w*CH + lane] = accA;
    zr[512 + w*CH + lane] = accB;
    __syncthreads();
    if (w < 2) {
        float s = 0.f;
        #pragma unroll
        for (int q = 0; q < 16; q++) s += zr[w*512 + q*CH + lane];
        zr[w*512 + lane] = s * (1.f/512.f);   // zbar[br][lane] at zr[br*512 + c]
    }
    __syncthreads();

    // Phase C: pooled = zbar @ W2 + b2   (2 rows of 768)
    for (int j = t; j < HIDDIM; j += 512) {
        float a0 = b2[j], a1 = a0;
        #pragma unroll
        for (int c = 0; c < CH; c++) {
            float wv = W2[c*HIDDIM + j];
            a0 += zr[c] * wv;
            a1 += zr[512 + c] * wv;
        }
        g_pooled[b*HIDDIM + j] = a0;
        g_pooled[(32 + b)*HIDDIM + j] = a1;
    }
}

// ================= K3: out = tanh(pooled @ Wo1 + bo1) =================
__global__ void k4b_out(const float* __restrict__ Wo1, const float* __restrict__ bo1) {
    __shared__ float As[16][64];
    __shared__ float Bs[64][16];
    int tx = threadIdx.x, ty = threadIdx.y;
    int tid = ty*16 + tx;
    int row = blockIdx.y*16 + ty;
    int col = blockIdx.x*16 + tx;
    float acc = 0.f;
    for (int kb = 0; kb < HIDDIM; kb += 64) {
        #pragma unroll
        for (int q = 0; q < 4; q++) {
            int lin = tid + 256*q; int r = lin >> 6, k = lin & 63;
            As[r][k] = g_pooled[(blockIdx.y*16 + r)*HIDDIM + kb + k];
        }
        #pragma unroll
        for (int q = 0; q < 4; q++) {
            int lin = tid + 256*q; int k = lin >> 4, c = lin & 15;
            Bs[k][c] = Wo1[(kb + k)*HIDDIM + blockIdx.x*16 + c];
        }
        __syncthreads();
        #pragma unroll
        for (int kk = 0; kk < 64; kk++) acc += As[ty][kk] * Bs[kk][tx];
        __syncthreads();
    }
    g_outv[row*HIDDIM + col] = tanhf(acc + bo1[col]);
}

// ================= K4: tail — logits+NLL+SimCSE+final =================
__global__ void k5_tail(const float* __restrict__ Wo2, const float* __restrict__ bo2,
                        const int* __restrict__ label, float* __restrict__ out, int out_size) {
    __shared__ float prow[HIDDIM];
    __shared__ float lg[16];
    __shared__ float dotc[64], normc[64], sims[64];
    int y = blockIdx.x;
    int t = threadIdx.x, w = t >> 5, lane = t & 31;

    // ---- logits for row rb = y ----
    const float* orow = &g_outv[y*HIDDIM];
    for (int lab = w; lab < LAB; lab += 8) {
        float s = 0.f;
        for (int k = lane; k < HIDDIM; k += 32) s += orow[k] * Wo2[k*LAB + lab];
        #pragma unroll
        for (int o = 16; o; o >>= 1) s += __shfl_xor_sync(0xffffffffu, s, o);
        if (!lane) lg[lab] = s + bo2[lab];
    }
    // ---- stage SimCSE row pr = (y&1)*32 + (y>>1) ----
    int pr = (y & 1)*32 + (y >> 1);
    const float* prg = &g_outv[pr*HIDDIM];
    for (int k = t; k < HIDDIM; k += 256) prow[k] = prg[k];
    __syncthreads();

    // NLL for row y
    if (t == 0) {
        float m = -1e30f;
        #pragma unroll
        for (int j = 0; j < LAB; j++) m = fmaxf(m, lg[j]);
        float e = 0.f;
        #pragma unroll
        for (int j = 0; j < LAB; j++) e += expf(lg[j] - m);
        float lse = m + logf(e);
        float nll = -(lg[label[y & 31]] - lse);
        atomicAdd(&g_loss, nll * (1.f/32.f));
    }
    // output logits (branch-0 rows 0..31)
    int base = (out_size > 320) ? 1 : 0;
    if (y < 32 && t < LAB) {
        int idx = base + y*LAB + t;
        if (idx < out_size) out[idx] = lg[t];
    }

    // ---- sims: dots of prow with all 64 interleaved rows ----
    for (int c = w; c < 64; c += 8) {
        const float* pc = &g_outv[((c & 1)*32 + (c >> 1))*HIDDIM];
        float d = 0.f, nn = 0.f;
        for (int k = lane; k < HIDDIM; k += 32) {
            float v = pc[k];
            d += prow[k] * v;
            nn += v * v;
        }
        #pragma unroll
        for (int o = 16; o; o >>= 1) {
            d  += __shfl_xor_sync(0xffffffffu, d, o);
            nn += __shfl_xor_sync(0xffffffffu, nn, o);
        }
        if (!lane) { dotc[c] = d; normc[c] = nn; }
    }
    __syncthreads();
    if (t < 64) {
        float invy = 1.f / fmaxf(sqrtf(normc[y]), 1e-8f);   // note: normc[y] == ||prow||^2 since dot(y,y)
        float invc = 1.f / fmaxf(sqrtf(normc[t]), 1e-8f);
        float v = dotc[t] * invy * invc;
        if (t == y) v -= 1e12f;
        sims[t] = v * 20.0f;
    }
    __syncthreads();
    if (t < 32) {
        float a = sims[t], bb2 = sims[t + 32];
        float m = fmaxf(a, bb2);
        #pragma unroll
        for (int o = 16; o; o >>= 1) m = fmaxf(m, __shfl_xor_sync(0xffffffffu, m, o));
        float e = expf(a - m) + expf(bb2 - m);
        #pragma unroll
        for (int o = 16; o; o >>= 1) e += __shfl_xor_sync(0xffffffffu, e, o);
        if (t == 0) {
            float lse = m + logf(e);
            int partner = y ^ 1;
            atomicAdd(&g_loss, (-(sims[partner] - lse)) * (1.f/64.f));
        }
    }
    // ---- last-block finalizer ----
    __syncthreads();
    if (t == 0) {
        __threadfence();
        int tk = atomicAdd(&g_ticket, 1);
        if (tk == 63 && base == 1) {
            float total = atomicAdd(&g_loss, 0.f);
            out[0] = total;
        }
    }
}

extern "C" void kernel_launch(void* const* d_in, const int* in_sizes, int n_in,
                              void* d_out, int out_size) {
    const int*   src    = (const int*)  d_in[0];
    const int*   other  = (const int*)  d_in[1];
    const int*   label  = (const int*)  d_in[2];
    const float* feat   = (const float*)d_in[3];
    const float* EM     = (const float*)d_in[4];
    const float* W1     = (const float*)d_in[5];
    const float* asrc1  = (const float*)d_in[6];
    const float* adst1  = (const float*)d_in[7];
    const float* b1     = (const float*)d_in[8];
    const float* W2     = (const float*)d_in[9];
    const float* asrc2  = (const float*)d_in[10];
    const float* adst2  = (const float*)d_in[11];
    const float* b2     = (const float*)d_in[12];
    const float* Wo1    = (const float*)d_in[13];
    const float* bo1    = (const float*)d_in[14];
    const float* Wo2    = (const float*)d_in[15];
    const float* bo2    = (const float*)d_in[16];
    float* out = (float*)d_out;

    static bool attr_set = false;
    if (!attr_set) {
        cudaFuncSetAttribute(k2_seq, cudaFuncAttributeMaxDynamicSharedMemorySize, 152000);
        attr_set = true;
    }

    k1_fused<<<129, 256>>>(feat, W1, W2, asrc2, adst2, asrc1, adst1);
    k2_seq<<<32, 512, 151552>>>(src, other, EM, b1, W2, b2);
    k4b_out<<<dim3(48, 4), dim3(16, 16)>>>(Wo1, bo1);
    k5_tail<<<64, 256>>>(Wo2, bo2, label, out, out_size);
}

// round 5
// speedup vs baseline: 1.2058x; 1.1452x over previous
#include <cuda_runtime.h>
#include <cuda_bf16.h>
#include <mma.h>
#include <math.h>
#include <stdint.h>

using namespace nvcuda;

#define NN 16384
#define BATCH 32
#define SEQ 512
#define HIDDIM 768
#define CH 32
#define VSZ 8192
#define LAB 10

// ---------------- device scratch ----------------
__device__ float g_h1[NN*CH];
__device__ float g_as1[NN*2];
__device__ float g_ad1[NN*2];
__device__ float4 g_ew4[NN];          // {ewp1, ewn1, ewp2, ewn2}
__device__ float g_r[2][NN*CH];
__device__ float g_as2[2][NN];
__device__ float g_ad2[2][NN];
__device__ float g_w2s[CH];
__device__ float g_w2d[CH];
__device__ float g_zpart[2][BATCH][4][CH];
__device__ float g_pooled[64*HIDDIM];
__device__ float g_outv[64*HIDDIM];
__device__ float g_loss;
__device__ int   g_ticket;

__device__ __forceinline__ float lrelu(float x){ return x > 0.f ? x : 0.2f*x; }

// ================= K1: h1 = feat@W1 via WMMA bf16 4-term split ==============
// grid 161: blocks 0..127 GEMM tiles (128 rows each); 128 = prep; 129..160 = EM gather
__global__ void __launch_bounds__(256)
k1_wmma(const float* __restrict__ feat, const float* __restrict__ W1,
        const float* __restrict__ W2,
        const float* __restrict__ att_src2, const float* __restrict__ att_dst2,
        const float* __restrict__ att_src1, const float* __restrict__ att_dst1,
        const int* __restrict__ tokA, const int* __restrict__ tokB,
        const float* __restrict__ EM) {
    if (blockIdx.x == 128) {
        // prep: w2s/w2d + zero accumulators
        int lane = threadIdx.x & 31, w = threadIdx.x >> 5;
        if (threadIdx.x == 0) { g_loss = 0.f; g_ticket = 0; }
        for (int c = w; c < CH; c += 8) {
            float ss = 0.f, sd = 0.f;
            for (int k = lane; k < HIDDIM; k += 32) {
                float wv = W2[c*HIDDIM + k];
                ss += wv * att_src2[k];
                sd += wv * att_dst2[k];
            }
            #pragma unroll
            for (int o = 16; o; o >>= 1) {
                ss += __shfl_xor_sync(0xffffffffu, ss, o);
                sd += __shfl_xor_sync(0xffffffffu, sd, o);
            }
            if (!lane) { g_w2s[c] = ss; g_w2d[c] = sd; }
        }
        return;
    }
    if (blockIdx.x > 128) {
        // EM gather: 32 blocks x 256 threads, 2 nodes per thread
        int gb = blockIdx.x - 129;
        #pragma unroll
        for (int j = 0; j < 2; j++) {
            int i = gb*512 + j*256 + threadIdx.x;
            int pos = i & (SEQ-1);
            bool hasP = pos > 0, hasN = pos < SEQ-1;
            int ta = tokA[i], tb = tokB[i];
            float4 v;
            v.x = hasP ? EM[tokA[i-1]*VSZ + ta] : 0.f;
            v.y = hasN ? EM[tokA[i+1]*VSZ + ta] : 0.f;
            v.z = hasP ? EM[tokB[i-1]*VSZ + tb] : 0.f;
            v.w = hasN ? EM[tokB[i+1]*VSZ + tb] : 0.f;
            g_ew4[i] = v;
        }
        return;
    }

    // ---- GEMM tile: 128 rows x 32 cols ----
    __shared__ union {
        struct {
            __nv_bfloat16 Ahi[128][72];
            __nv_bfloat16 Alo[128][72];
            __nv_bfloat16 Bhi[32][72];
            __nv_bfloat16 Blo[32][72];
        } s;
        float Cs[128][36];   // ldm 36: multiple of 4 elements (store_matrix_sync req)
    } u;
    __shared__ float sAs[CH], sAd[CH];

    int tid = threadIdx.x, wid = tid >> 5;
    int rowBase = blockIdx.x * 128;
    if (tid < CH) { sAs[tid] = att_src1[tid]; sAd[tid] = att_dst1[tid]; }

    wmma::fragment<wmma::accumulator, 16, 16, 16, float> acc[2];
    wmma::fill_fragment(acc[0], 0.f);
    wmma::fill_fragment(acc[1], 0.f);

    for (int kb = 0; kb < HIDDIM; kb += 64) {
        // stage A: 128 x 64 fp32 -> hi/lo bf16
        {
            int r = tid >> 1, h = tid & 1;
            const float4* fr = (const float4*)&feat[(size_t)(rowBase + r)*HIDDIM + kb + h*32];
            #pragma unroll
            for (int q = 0; q < 8; q++) {
                float4 v = fr[q];
                int col = h*32 + q*4;
                __nv_bfloat162 h01 = __floats2bfloat162_rn(v.x, v.y);
                __nv_bfloat162 h23 = __floats2bfloat162_rn(v.z, v.w);
                *(__nv_bfloat162*)&u.s.Ahi[r][col]   = h01;
                *(__nv_bfloat162*)&u.s.Ahi[r][col+2] = h23;
                float lx = v.x - __low2float(h01),  ly = v.y - __high2float(h01);
                float lz = v.z - __low2float(h23),  lw = v.w - __high2float(h23);
                *(__nv_bfloat162*)&u.s.Alo[r][col]   = __floats2bfloat162_rn(lx, ly);
                *(__nv_bfloat162*)&u.s.Alo[r][col+2] = __floats2bfloat162_rn(lz, lw);
            }
        }
        // stage B: W1[kb+k][n] -> Bhi/Blo[n][k]  (col-major for wmma matrix_b)
        #pragma unroll
        for (int q = 0; q < 8; q++) {
            int e = q*256 + tid;
            int k = e >> 5, n = e & 31;
            float wv = W1[(size_t)(kb + k)*CH + n];
            __nv_bfloat16 hi = __float2bfloat16(wv);
            float lo = wv - __bfloat162float(hi);
            u.s.Bhi[n][k] = hi;
            u.s.Blo[n][k] = __float2bfloat16(lo);
        }
        __syncthreads();

        #pragma unroll
        for (int kk = 0; kk < 4; kk++) {
            wmma::fragment<wmma::matrix_a, 16, 16, 16, __nv_bfloat16, wmma::row_major> a_hi, a_lo;
            wmma::load_matrix_sync(a_hi, &u.s.Ahi[wid*16][kk*16], 72);
            wmma::load_matrix_sync(a_lo, &u.s.Alo[wid*16][kk*16], 72);
            #pragma unroll
            for (int ct = 0; ct < 2; ct++) {
                wmma::fragment<wmma::matrix_b, 16, 16, 16, __nv_bfloat16, wmma::col_major> b_hi, b_lo;
                wmma::load_matrix_sync(b_hi, &u.s.Bhi[ct*16][kk*16], 72);
                wmma::load_matrix_sync(b_lo, &u.s.Blo[ct*16][kk*16], 72);
                wmma::mma_sync(acc[ct], a_hi, b_hi, acc[ct]);
                wmma::mma_sync(acc[ct], a_hi, b_lo, acc[ct]);
                wmma::mma_sync(acc[ct], a_lo, b_hi, acc[ct]);
                wmma::mma_sync(acc[ct], a_lo, b_lo, acc[ct]);
            }
        }
        __syncthreads();
    }

    // epilogue: dump accumulators to smem, then per-row writes + attention dots
    wmma::store_matrix_sync(&u.Cs[wid*16][0],  acc[0], 36, wmma::mem_row_major);
    wmma::store_matrix_sync(&u.Cs[wid*16][16], acc[1], 36, wmma::mem_row_major);
    __syncthreads();
    if (tid < 128) {
        int r = rowBase + tid;
        float ss0 = 0.f, sd0 = 0.f, ss1 = 0.f, sd1 = 0.f;
        #pragma unroll
        for (int q = 0; q < 8; q++) {
            float4 v = { u.Cs[tid][q*4+0], u.Cs[tid][q*4+1], u.Cs[tid][q*4+2], u.Cs[tid][q*4+3] };
            *(float4*)&g_h1[r*CH + q*4] = v;
            float ps = v.x*sAs[q*4+0] + v.y*sAs[q*4+1] + v.z*sAs[q*4+2] + v.w*sAs[q*4+3];
            float pd = v.x*sAd[q*4+0] + v.y*sAd[q*4+1] + v.z*sAd[q*4+2] + v.w*sAd[q*4+3];
            if (q < 4) { ss0 += ps; sd0 += pd; } else { ss1 += ps; sd1 += pd; }
        }
        g_as1[r*2 + 0] = ss0; g_ad1[r*2 + 0] = sd0;
        g_as1[r*2 + 1] = ss1; g_ad1[r*2 + 1] = sd1;
    }
}

// ================= K2: conv1 aggregate (both branches) + relu + conv2 dots =========
__global__ void k2_conv1(const float* __restrict__ b1) {
    int i = (blockIdx.x*blockDim.x + threadIdx.x) >> 5;
    int lane = threadIdx.x & 31;
    if (i >= NN) return;
    int pos = i & (SEQ-1);
    bool hasP = pos > 0, hasN = pos < SEQ-1;
    int hh = lane >> 4;

    float adi = g_ad1[i*2 + hh];
    float es = lrelu(g_as1[i*2 + hh] + adi);
    float ep = hasP ? lrelu(g_as1[(i-1)*2 + hh] + adi) : -1e30f;
    float en = hasN ? lrelu(g_as1[(i+1)*2 + hh] + adi) : -1e30f;
    float m  = fmaxf(es, fmaxf(ep, en));
    float xs = expf(es - m);
    float xp = hasP ? expf(ep - m) : 0.f;
    float xn = hasN ? expf(en - m) : 0.f;
    float inv = 1.f / (xs + xp + xn + 1e-16f);
    float as_ = xs*inv, ap = xp*inv, an = xn*inv;

    float4 ewv = g_ew4[i];

    float hp = hasP ? g_h1[(i-1)*CH + lane] : 0.f;
    float hs = g_h1[i*CH + lane];
    float hn = hasN ? g_h1[(i+1)*CH + lane] : 0.f;
    float bb = b1[lane];

    float r1 = fmaxf(0.f, ap*ewv.x*hp + as_*hs + an*ewv.y*hn + bb);
    float r2 = fmaxf(0.f, ap*ewv.z*hp + as_*hs + an*ewv.w*hn + bb);
    g_r[0][i*CH + lane] = r1;
    g_r[1][i*CH + lane] = r2;

    float ws2 = g_w2s[lane], wd2 = g_w2d[lane];
    float v0 = r1*ws2, v1 = r1*wd2, v2 = r2*ws2, v3 = r2*wd2;
    #pragma unroll
    for (int o = 16; o; o >>= 1) {
        v0 += __shfl_xor_sync(0xffffffffu, v0, o);
        v1 += __shfl_xor_sync(0xffffffffu, v1, o);
        v2 += __shfl_xor_sync(0xffffffffu, v2, o);
        v3 += __shfl_xor_sync(0xffffffffu, v3, o);
    }
    if (!lane) {
        g_as2[0][i] = v0; g_ad2[0][i] = v1;
        g_as2[1][i] = v2; g_ad2[1][i] = v3;
    }
}

// ================= K3: conv2 aggregate + pooled partial sums =================
__global__ void k3_zpart() {
    int b = blockIdx.x, q = blockIdx.y;
    int w = threadIdx.x >> 5, lane = threadIdx.x & 31;
    float acc0 = 0.f, acc1 = 0.f;
    for (int pp = w; pp < 128; pp += 8) {
        int pos = q*128 + pp;
        int i = b*SEQ + pos;
        bool hasP = pos > 0, hasN = pos < SEQ-1;
        #pragma unroll
        for (int br = 0; br < 2; br++) {
            float adi = g_ad2[br][i];
            float es = lrelu(g_as2[br][i] + adi);
            float ep = hasP ? lrelu(g_as2[br][i-1] + adi) : -1e30f;
            float en = hasN ? lrelu(g_as2[br][i+1] + adi) : -1e30f;
            float m  = fmaxf(es, fmaxf(ep, en));
            float xs = expf(es - m);
            float xp = hasP ? expf(ep - m) : 0.f;
            float xn = hasN ? expf(en - m) : 0.f;
            float inv = 1.f / (xs + xp + xn + 1e-16f);
            float z = xs*inv * g_r[br][i*CH + lane];
            if (hasP) z += xp*inv * g_r[br][(i-1)*CH + lane];
            if (hasN) z += xn*inv * g_r[br][(i+1)*CH + lane];
            if (br == 0) acc0 += z; else acc1 += z;
        }
    }
    __shared__ float sm[2][8][CH];
    sm[0][w][lane] = acc0;
    sm[1][w][lane] = acc1;
    __syncthreads();
    if (w < 2) {
        float s = 0.f;
        #pragma unroll
        for (int t = 0; t < 8; t++) s += sm[w][t][lane];
        g_zpart[w][b][q][lane] = s;
    }
}

// ================= K4a: pooled = zbar @ W2 + b2 =================
__global__ void k4a_pooled(const float* __restrict__ W2, const float* __restrict__ b2) {
    int blk = blockIdx.x; int br = blk >> 5, b = blk & 31;
    __shared__ float z[CH];
    if (threadIdx.x < CH) {
        float s = g_zpart[br][b][0][threadIdx.x] + g_zpart[br][b][1][threadIdx.x]
                + g_zpart[br][b][2][threadIdx.x] + g_zpart[br][b][3][threadIdx.x];
        z[threadIdx.x] = s * (1.f/512.f);
    }
    __syncthreads();
    for (int j = threadIdx.x; j < HIDDIM; j += 256) {
        float acc = b2[j];
        #pragma unroll
        for (int c = 0; c < CH; c++) acc += z[c] * W2[c*HIDDIM + j];
        g_pooled[(br*32 + b)*HIDDIM + j] = acc;
    }
}

// ================= K4b: out = tanh(pooled @ Wo1 + bo1) =================
__global__ void k4b_out(const float* __restrict__ Wo1, const float* __restrict__ bo1) {
    __shared__ float As[16][68];
    __shared__ float Bs[64][68];
    int tid = threadIdx.x;
    int tx = tid & 15, ty = tid >> 4;
    int colBase = blockIdx.x * 64, rowBase = blockIdx.y * 16;
    float acc[4] = {};
    for (int kb = 0; kb < HIDDIM; kb += 64) {
        #pragma unroll
        for (int q = 0; q < 4; q++) {
            int e = q*256 + tid; int r = e >> 6, k = e & 63;
            As[r][k] = g_pooled[(rowBase + r)*HIDDIM + kb + k];
        }
        #pragma unroll
        for (int q = 0; q < 16; q++) {
            int e = q*256 + tid; int k = e >> 6, c = e & 63;
            Bs[k][c] = Wo1[(size_t)(kb + k)*HIDDIM + colBase + c];
        }
        __syncthreads();
        #pragma unroll
        for (int kk = 0; kk < 64; kk++) {
            float a = As[ty][kk];
            float4 b4 = *(float4*)&Bs[kk][tx*4];
            acc[0] += a*b4.x; acc[1] += a*b4.y; acc[2] += a*b4.z; acc[3] += a*b4.w;
        }
        __syncthreads();
    }
    int row = rowBase + ty;
    #pragma unroll
    for (int j = 0; j < 4; j++) {
        int col = colBase + tx*4 + j;
        g_outv[row*HIDDIM + col] = tanhf(acc[j] + bo1[col]);
    }
}

// ================= K5: tail — logits+NLL+SimCSE+final =================
__global__ void k5_tail(const float* __restrict__ Wo2, const float* __restrict__ bo2,
                        const int* __restrict__ label, float* __restrict__ out, int out_size) {
    __shared__ __align__(16) float prow[HIDDIM];
    __shared__ __align__(16) float WoT[LAB][HIDDIM];
    __shared__ float lg[16];
    __shared__ float dotc[64], normc[64], sims[64];
    int y = blockIdx.x;
    int t = threadIdx.x, w = t >> 5, lane = t & 31;

    for (int e = t; e < LAB*HIDDIM; e += 256) {
        int k = e / LAB, lab = e - LAB*k;
        WoT[lab][k] = Wo2[e];
    }
    int pr = (y & 1)*32 + (y >> 1);
    const float4* prg = (const float4*)&g_outv[pr*HIDDIM];
    for (int k = t; k < HIDDIM/4; k += 256) ((float4*)prow)[k] = prg[k];
    __syncthreads();

    const float4* orow4 = (const float4*)&g_outv[y*HIDDIM];
    for (int lab = w; lab < LAB; lab += 8) {
        float s = 0.f;
        const float4* wr = (const float4*)&WoT[lab][0];
        #pragma unroll
        for (int i = 0; i < 6; i++) {
            float4 a = orow4[lane + 32*i];
            float4 b = wr[lane + 32*i];
            s += a.x*b.x + a.y*b.y + a.z*b.z + a.w*b.w;
        }
        #pragma unroll
        for (int o = 16; o; o >>= 1) s += __shfl_xor_sync(0xffffffffu, s, o);
        if (!lane) lg[lab] = s + bo2[lab];
    }

    for (int c = w; c < 64; c += 8) {
        int rc = (c & 1)*32 + (c >> 1);
        const float4* pc = (const float4*)&g_outv[rc*HIDDIM];
        float d = 0.f, nn = 0.f;
        #pragma unroll
        for (int i = 0; i < 6; i++) {
            float4 v = pc[lane + 32*i];
            float4 p = ((float4*)prow)[lane + 32*i];
            d  += p.x*v.x + p.y*v.y + p.z*v.z + p.w*v.w;
            nn += v.x*v.x + v.y*v.y + v.z*v.z + v.w*v.w;
        }
        #pragma unroll
        for (int o = 16; o; o >>= 1) {
            d  += __shfl_xor_sync(0xffffffffu, d, o);
            nn += __shfl_xor_sync(0xffffffffu, nn, o);
        }
        if (!lane) { dotc[c] = d; normc[c] = nn; }
    }
    __syncthreads();

    if (t == 0) {
        float m = -1e30f;
        #pragma unroll
        for (int j = 0; j < LAB; j++) m = fmaxf(m, lg[j]);
        float e = 0.f;
        #pragma unroll
        for (int j = 0; j < LAB; j++) e += expf(lg[j] - m);
        float lse = m + logf(e);
        float nll = -(lg[label[y & 31]] - lse);
        atomicAdd(&g_loss, nll * (1.f/32.f));
    }
    int base = (out_size > 320) ? 1 : 0;
    if (y < 32 && t < LAB) {
        int idx = base + y*LAB + t;
        if (idx < out_size) out[idx] = lg[t];
    }
    if (t < 64) {
        float invy = 1.f / fmaxf(sqrtf(normc[y]), 1e-8f);
        float invc = 1.f / fmaxf(sqrtf(normc[t]), 1e-8f);
        float v = dotc[t] * invy * invc;
        if (t == y) v -= 1e12f;
        sims[t] = v * 20.0f;
    }
    __syncthreads();
    if (t < 32) {
        float a = sims[t], bb2 = sims[t + 32];
        float m = fmaxf(a, bb2);
        #pragma unroll
        for (int o = 16; o; o >>= 1) m = fmaxf(m, __shfl_xor_sync(0xffffffffu, m, o));
        float e = expf(a - m) + expf(bb2 - m);
        #pragma unroll
        for (int o = 16; o; o >>= 1) e += __shfl_xor_sync(0xffffffffu, e, o);
        if (t == 0) {
            float lse = m + logf(e);
            int partner = y ^ 1;
            atomicAdd(&g_loss, (-(sims[partner] - lse)) * (1.f/64.f));
        }
    }
    __syncthreads();
    if (t == 0) {
        __threadfence();
        int tk = atomicAdd(&g_ticket, 1);
        if (tk == 63 && base == 1) {
            float total = atomicAdd(&g_loss, 0.f);
            out[0] = total;
        }
    }
}

extern "C" void kernel_launch(void* const* d_in, const int* in_sizes, int n_in,
                              void* d_out, int out_size) {
    const int*   src    = (const int*)  d_in[0];
    const int*   other  = (const int*)  d_in[1];
    const int*   label  = (const int*)  d_in[2];
    const float* feat   = (const float*)d_in[3];
    const float* EM     = (const float*)d_in[4];
    const float* W1     = (const float*)d_in[5];
    const float* asrc1  = (const float*)d_in[6];
    const float* adst1  = (const float*)d_in[7];
    const float* b1     = (const float*)d_in[8];
    const float* W2     = (const float*)d_in[9];
    const float* asrc2  = (const float*)d_in[10];
    const float* adst2  = (const float*)d_in[11];
    const float* b2     = (const float*)d_in[12];
    const float* Wo1    = (const float*)d_in[13];
    const float* bo1    = (const float*)d_in[14];
    const float* Wo2    = (const float*)d_in[15];
    const float* bo2    = (const float*)d_in[16];
    float* out = (float*)d_out;

    k1_wmma<<<161, 256>>>(feat, W1, W2, asrc2, adst2, asrc1, adst1, src, other, EM);
    k2_conv1<<<NN/8, 256>>>(b1);
    k3_zpart<<<dim3(BATCH, 4), 256>>>();
    k4a_pooled<<<64, 256>>>(W2, b2);
    k4b_out<<<dim3(12, 4), 256>>>(Wo1, bo1);
    k5_tail<<<64, 256>>>(Wo2, bo2, label, out, out_size);
}